// round 9
// baseline (speedup 1.0000x reference)
#include <cuda_runtime.h>
#include <cuda_fp16.h>
#include <math.h>
#include <stdint.h>

// Problem constants
#define BMAX   16384
#define INDIM  128
#define STATE  64
#define HID    1024
#define NB     8
#define KACT   (INDIM + INDIM * NB)   // 1152
#define NOUT2  (8192 + 64)            // 8256
#define NOUT2P 8448                   // padded to multiple of 256

// ---------------- scratch ----------------
__device__ float  g_x   [BMAX * INDIM];
__device__ __half g_act [BMAX * KACT];
__device__ __half g_kan [BMAX * HID];
__device__ __half g_W1T [HID * KACT];            // [o][k]
__device__ __half g_W2T [(size_t)NOUT2P * HID];  // [n][h], zero-padded rows
__device__ float  g_b2  [NOUT2];

// ---------------- helpers ----------------
__device__ __forceinline__ void ldsm4(uint32_t addr, uint32_t& r0, uint32_t& r1,
                                      uint32_t& r2, uint32_t& r3) {
    asm volatile("ldmatrix.sync.aligned.m8n8.x4.shared.b16 {%0,%1,%2,%3}, [%4];"
                 : "=r"(r0), "=r"(r1), "=r"(r2), "=r"(r3) : "r"(addr));
}

__device__ __forceinline__ void mma_f16(float* d, const uint32_t* a, const uint32_t* b) {
    asm volatile(
        "mma.sync.aligned.m16n8k16.row.col.f32.f16.f16.f32 "
        "{%0,%1,%2,%3}, {%4,%5,%6,%7}, {%8,%9}, {%0,%1,%2,%3};"
        : "+f"(d[0]), "+f"(d[1]), "+f"(d[2]), "+f"(d[3])
        : "r"(a[0]), "r"(a[1]), "r"(a[2]), "r"(a[3]), "r"(b[0]), "r"(b[1]));
}

__device__ __forceinline__ void cpa16(uint32_t smem, const void* g) {
    asm volatile("cp.async.cg.shared.global [%0], [%1], 16;" :: "r"(smem), "l"(g));
}
__device__ __forceinline__ void cpa_commit() { asm volatile("cp.async.commit_group;"); }
__device__ __forceinline__ void cpa_wait1()  { asm volatile("cp.async.wait_group 1;"); }

// ---------------- merged prep kernel ----------------
#define NB_W2T ((NOUT2P / 32) * (HID / 32))
#define NB_W1T ((HID * KACT + 255) / 256)
#define NB_B2  ((NOUT2 + 255) / 256)

__global__ __launch_bounds__(256) void prep_all(const float* __restrict__ scale_base,
                                                const float* __restrict__ scale_sp,
                                                const float* __restrict__ coef,
                                                const float* __restrict__ f_w,
                                                const float* __restrict__ bias_w,
                                                const float* __restrict__ f_b,
                                                const float* __restrict__ bias_b) {
    int bx = blockIdx.x;
    int tid = threadIdx.x;
    if (bx < NB_W2T) {
        __shared__ float tile[32][33];
        int tileN = bx % (NOUT2P / 32), tileH = bx / (NOUT2P / 32);
        int n0 = tileN * 32, h0 = tileH * 32;
        int tx = tid & 31, ty0 = tid >> 5;
#pragma unroll
        for (int p = 0; p < 4; p++) {
            int ty = ty0 + p * 8;
            int n = n0 + tx;
            float v = 0.0f;
            if (n < 8192)       v = f_w[(size_t)(h0 + ty) * 8192 + n];
            else if (n < NOUT2) v = bias_w[(h0 + ty) * 64 + (n - 8192)];
            tile[ty][tx] = v;
        }
        __syncthreads();
#pragma unroll
        for (int p = 0; p < 4; p++) {
            int ty = ty0 + p * 8;
            g_W2T[(size_t)(n0 + ty) * HID + h0 + tx] = __float2half(tile[tx][ty]);
        }
    } else if (bx < NB_W2T + NB_W1T) {
        int idx = (bx - NB_W2T) * 256 + tid;
        if (idx >= HID * KACT) return;
        int o = idx / KACT, k = idx - o * KACT;
        float v;
        if (k < INDIM) {
            v = scale_base[k * HID + o];
        } else {
            int kk = k - INDIM;
            int i = kk >> 3, c = kk & 7;
            v = scale_sp[i * HID + o] * coef[(i * HID + o) * NB + c];
        }
        g_W1T[idx] = __float2half(v);
    } else {
        int idx = (bx - NB_W2T - NB_B2 * 0 - NB_W1T) * 256 + tid;
        if (idx >= NOUT2) return;
        g_b2[idx] = (idx < 8192) ? f_b[idx] : bias_b[idx - 8192];
    }
}

// ---------------- activation build ----------------
__device__ __forceinline__ float knot(int j) { return -1.0f + 0.4f * (float)(j - 3); }

__global__ void build_act(const float* __restrict__ state,
                          const float* __restrict__ novelU, int B) {
    int idx = blockIdx.x * blockDim.x + threadIdx.x;
    if (idx >= B * INDIM) return;
    int b = idx / INDIM, i = idx - b * INDIM;
    float x = (i < STATE) ? state[b * STATE + i] : novelU[b * (INDIM - STATE) + (i - STATE)];
    g_x[b * INDIM + i] = x;
    g_act[(size_t)b * KACT + i] = __float2half(x / (1.0f + expf(-x)));
    float bb[11];
#pragma unroll
    for (int j = 0; j < 11; j++)
        bb[j] = (x >= knot(j) && x < knot(j + 1)) ? 1.0f : 0.0f;
#pragma unroll
    for (int ord = 1; ord <= 3; ord++) {
#pragma unroll
        for (int j = 0; j < 11 - 1; j++) {
            if (j >= 11 - ord) break;
            float l = (x - knot(j)) / (knot(j + ord) - knot(j));
            float r = (knot(j + ord + 1) - x) / (knot(j + ord + 1) - knot(j + 1));
            bb[j] = l * bb[j] + r * bb[j + 1];
        }
    }
    __half2 h0 = __floats2half2_rn(bb[0], bb[1]);
    __half2 h1 = __floats2half2_rn(bb[2], bb[3]);
    __half2 h2 = __floats2half2_rn(bb[4], bb[5]);
    __half2 h3 = __floats2half2_rn(bb[6], bb[7]);
    uint4 pack = make_uint4(*(uint32_t*)&h0, *(uint32_t*)&h1, *(uint32_t*)&h2, *(uint32_t*)&h3);
    *(uint4*)&g_act[(size_t)b * KACT + INDIM + i * NB] = pack;
}

// ---------------- FP16 tensor-core GEMM ------------------------------------
// CTA tile 128x256, 256 threads (8 warps, warp tile 64x64), KC=64,
// 3-stage cp.async ring, one __syncthreads per chunk.
#define KC    64
#define SAH   72
#define STG_H ((128 + 256) * SAH)
#define STGB  (STG_H * 2)
#define XSP   130

template<int K, bool EPI2>
__global__ __launch_bounds__(256) void mma_gemm(const __half* __restrict__ A,
                                                const __half* __restrict__ Bt,
                                                __half* __restrict__ C,
                                                float* __restrict__ outAB,
                                                float* __restrict__ outBias,
                                                float* __restrict__ outO) {
    extern __shared__ char dynsmem[];
    uint32_t smem_addr = (uint32_t)__cvta_generic_to_shared(dynsmem);

    int tid = threadIdx.x;
    int lane = tid & 31, wid = tid >> 5;        // wid 0..7
    int row0 = blockIdx.y * 128, col0 = blockIdx.x * 256;
    int m0w = (wid & 1) * 64;                   // 2 m-warps
    int n0w = (wid >> 1) * 64;                  // 4 n-warps x 64 cols

    int rowA = lane & 15;
    int kAh  = 8 * (lane >> 4);
    int rowB = (lane & 7) + 8 * (lane >> 4);
    int kBh  = 8 * ((lane >> 3) & 1);

    float acc[4][8][4];
#pragma unroll
    for (int mt = 0; mt < 4; mt++)
#pragma unroll
        for (int nt = 0; nt < 8; nt++)
#pragma unroll
            for (int j = 0; j < 4; j++) acc[mt][nt][j] = 0.0f;

    const int nk = K / KC;

    auto load_stage = [&](int stg, int k0) {
        uint32_t base = smem_addr + stg * STGB;
#pragma unroll
        for (int c = 0; c < 12; c++) {
            int ch  = tid + c * 256;         // 0..3071
            int r   = ch >> 3;               // 0..383
            int off = (ch & 7) * 8;
            const __half* src = (r < 128)
                ? A  + (size_t)(row0 + r) * K + k0 + off
                : Bt + (size_t)(col0 + (r - 128)) * K + k0 + off;
            cpa16(base + (uint32_t)(r * SAH + off) * 2, src);
        }
    };

    load_stage(0, 0);
    cpa_commit();
    load_stage(1, KC);
    cpa_commit();

    for (int it = 0; it < nk; it++) {
        int cur = it % 3;
        cpa_wait1();
        __syncthreads();
        int nx = it + 2;
        if (nx < nk) load_stage(nx % 3, nx * KC);
        cpa_commit();

        uint32_t sA = smem_addr + cur * STGB;
        uint32_t sB = sA + 128 * SAH * 2;
#pragma unroll
        for (int ks = 0; ks < 4; ks++) {
            int kh = ks * 16;
            uint32_t a[4][4], b[4][4];
#pragma unroll
            for (int mt = 0; mt < 4; mt++) {
                uint32_t addr = sA + (uint32_t)((m0w + mt * 16 + rowA) * SAH + kh + kAh) * 2;
                ldsm4(addr, a[mt][0], a[mt][1], a[mt][2], a[mt][3]);
            }
#pragma unroll
            for (int ng = 0; ng < 4; ng++) {
                uint32_t addr = sB + (uint32_t)((n0w + ng * 16 + rowB) * SAH + kh + kBh) * 2;
                ldsm4(addr, b[ng][0], b[ng][1], b[ng][2], b[ng][3]);
            }
#pragma unroll
            for (int mt = 0; mt < 4; mt++)
#pragma unroll
                for (int nt = 0; nt < 8; nt++)
                    mma_f16(acc[mt][nt], a[mt], &b[nt >> 1][(nt & 1) * 2]);
        }
    }

    int gid = lane >> 2, tig = lane & 3;

    // ---- matrix stores ----
#pragma unroll
    for (int mt = 0; mt < 4; mt++) {
#pragma unroll
        for (int nt = 0; nt < 8; nt++) {
            int r0r = row0 + m0w + mt * 16 + gid;
            int n   = col0 + n0w + nt * 8 + 2 * tig;
            if (!EPI2) {
                __half2 v01 = __floats2half2_rn(acc[mt][nt][0], acc[mt][nt][1]);
                __half2 v23 = __floats2half2_rn(acc[mt][nt][2], acc[mt][nt][3]);
                *(__half2*)(C + (size_t)r0r * HID + n)       = v01;
                *(__half2*)(C + (size_t)(r0r + 8) * HID + n) = v23;
            } else {
                if (n >= NOUT2) continue;
                float b0 = g_b2[n], b1 = g_b2[n + 1];
                float2 v01 = make_float2(acc[mt][nt][0] + b0, acc[mt][nt][1] + b1);
                float2 v23 = make_float2(acc[mt][nt][2] + b0, acc[mt][nt][3] + b1);
                if (n < 8192) {
                    *(float2*)(outAB + (size_t)r0r * 8192 + n)       = v01;
                    *(float2*)(outAB + (size_t)(r0r + 8) * 8192 + n) = v23;
                } else {
                    int nb = n - 8192;
                    *(float2*)(outBias + (size_t)r0r * 64 + nb)       = v01;
                    *(float2*)(outBias + (size_t)(r0r + 8) * 64 + nb) = v23;
                }
            }
        }
    }

    // ---- fused out = (AB + f_b tile) . x ; 256-col tile = 2 s values ----
    if (EPI2 && col0 < 8192) {
        float* xs  = (float*)dynsmem;            // [128][XSP]
        float* red = xs + 128 * XSP;             // [2 jj][2 sl][128 rows]
        __syncthreads();
        for (int i = tid * 4; i < 128 * 128; i += 256 * 4) {
            int r = i >> 7, u = i & 127;
            float4 v = *(const float4*)(g_x + (size_t)(row0 + r) * INDIM + u);
            xs[r * XSP + u]     = v.x;
            xs[r * XSP + u + 1] = v.y;
            xs[r * XSP + u + 2] = v.z;
            xs[r * XSP + u + 3] = v.w;
        }
        __syncthreads();

        int g  = wid >> 1;         // n-group 0..3 (64 cols each)
        int sl = g >> 1;           // s_local 0/1
        int jj = g & 1;            // reduction slot 0/1
#pragma unroll
        for (int mt = 0; mt < 4; mt++) {
            int lr = m0w + mt * 16 + gid;
            float p0 = 0.0f, p1 = 0.0f;
#pragma unroll
            for (int nt = 0; nt < 8; nt++) {
                int u  = n0w + nt * 8 + 2 * tig;    // 0..255
                int ux = u & 127;
                float n_b0 = g_b2[col0 + u], n_b1 = g_b2[col0 + u + 1];
                float x00 = xs[lr * XSP + ux],       x01 = xs[lr * XSP + ux + 1];
                float x10 = xs[(lr + 8) * XSP + ux], x11 = xs[(lr + 8) * XSP + ux + 1];
                p0 = fmaf(acc[mt][nt][0] + n_b0, x00, p0);
                p0 = fmaf(acc[mt][nt][1] + n_b1, x01, p0);
                p1 = fmaf(acc[mt][nt][2] + n_b0, x10, p1);
                p1 = fmaf(acc[mt][nt][3] + n_b1, x11, p1);
            }
            p0 += __shfl_xor_sync(0xffffffff, p0, 1);
            p0 += __shfl_xor_sync(0xffffffff, p0, 2);
            p1 += __shfl_xor_sync(0xffffffff, p1, 1);
            p1 += __shfl_xor_sync(0xffffffff, p1, 2);
            if (tig == 0) {
                red[(jj * 2 + sl) * 128 + lr]     = p0;
                red[(jj * 2 + sl) * 128 + lr + 8] = p1;
            }
        }
        __syncthreads();
        if (tid < 256) {
            int srow = tid & 127, s_l = tid >> 7;
            float v = red[(0 * 2 + s_l) * 128 + srow] + red[(1 * 2 + s_l) * 128 + srow];
            outO[(size_t)(row0 + srow) * 64 + (col0 >> 7) + s_l] = v;
        }
    }
}

// ---------------- out += bias ----------------
__global__ void add_bias(const float* __restrict__ biasOut, float* __restrict__ outO, int n) {
    int i = blockIdx.x * blockDim.x + threadIdx.x;
    if (i < n) outO[i] += biasOut[i];
}

// ---------------- launch ----------------
extern "C" void kernel_launch(void* const* d_in, const int* in_sizes, int n_in,
                              void* d_out, int out_size) {
    const float* novelU     = (const float*)d_in[0];
    const float* state      = (const float*)d_in[1];
    const float* coef       = (const float*)d_in[2];
    const float* scale_base = (const float*)d_in[3];
    const float* scale_sp   = (const float*)d_in[4];
    const float* bias_w     = (const float*)d_in[5];
    const float* bias_b     = (const float*)d_in[6];
    const float* f_w        = (const float*)d_in[7];
    const float* f_b        = (const float*)d_in[8];
    float* out = (float*)d_out;

    int B = in_sizes[0] / 64;
    if (B > BMAX) B = BMAX;

    float* outO    = out;
    float* outAB   = out + (size_t)B * 64;
    float* outBias = out + (size_t)B * 64 + (size_t)B * 8192;

    prep_all<<<NB_W2T + NB_W1T + NB_B2, 256>>>(scale_base, scale_sp, coef,
                                               f_w, bias_w, f_b, bias_b);
    build_act<<<(B * INDIM + 255) / 256, 256>>>(state, novelU, B);

    __half *d_kan, *d_act, *d_W1T, *d_W2T;
    cudaGetSymbolAddress((void**)&d_kan, g_kan);
    cudaGetSymbolAddress((void**)&d_act, g_act);
    cudaGetSymbolAddress((void**)&d_W1T, g_W1T);
    cudaGetSymbolAddress((void**)&d_W2T, g_W2T);

    const int smem_stage = 3 * STGB;
    const int smem_epi   = 128 * XSP * 4 + 4 * 128 * 4;
    const int smem_bytes = smem_epi > smem_stage ? smem_epi : smem_stage;
    static bool attr_set = false;
    if (!attr_set) {
        cudaFuncSetAttribute(mma_gemm<KACT, false>,
                             cudaFuncAttributeMaxDynamicSharedMemorySize, smem_bytes);
        cudaFuncSetAttribute(mma_gemm<HID, true>,
                             cudaFuncAttributeMaxDynamicSharedMemorySize, smem_bytes);
        attr_set = true;
    }

    dim3 g1(HID / 256, B / 128);
    mma_gemm<KACT, false><<<g1, 256, smem_bytes>>>(d_act, d_W1T, d_kan, nullptr, nullptr, nullptr);

    dim3 g2(NOUT2P / 256, B / 128);
    mma_gemm<HID, true><<<g2, 256, smem_bytes>>>(d_kan, d_W2T, nullptr, outAB, outBias, outO);

    add_bias<<<(B * 64 + 255) / 256, 256>>>(outBias, outO, B * 64);
}

// round 10
// speedup vs baseline: 1.0422x; 1.0422x over previous
#include <cuda_runtime.h>
#include <cuda_fp16.h>
#include <math.h>
#include <stdint.h>

// Problem constants
#define BMAX   16384
#define INDIM  128
#define STATE  64
#define HID    1024
#define NB     8
#define KACT   (INDIM + INDIM * NB)   // 1152
#define NOUT2  (8192 + 64)            // 8256
#define NOUT2P 8448                   // padded to multiple of 256

// ---------------- scratch ----------------
__device__ float  g_x   [BMAX * INDIM];
__device__ __half g_act [BMAX * KACT];
__device__ __half g_kan [BMAX * HID];
__device__ __half g_W1T [HID * KACT];            // [o][k]
__device__ __half g_W2T [(size_t)NOUT2P * HID];  // [n][h], zero-padded rows
__device__ float  g_b2  [NOUT2];

// ---------------- helpers ----------------
__device__ __forceinline__ void ldsm4(uint32_t addr, uint32_t& r0, uint32_t& r1,
                                      uint32_t& r2, uint32_t& r3) {
    asm volatile("ldmatrix.sync.aligned.m8n8.x4.shared.b16 {%0,%1,%2,%3}, [%4];"
                 : "=r"(r0), "=r"(r1), "=r"(r2), "=r"(r3) : "r"(addr));
}

__device__ __forceinline__ void mma_f16(float* d, const uint32_t* a, const uint32_t* b) {
    asm volatile(
        "mma.sync.aligned.m16n8k16.row.col.f32.f16.f16.f32 "
        "{%0,%1,%2,%3}, {%4,%5,%6,%7}, {%8,%9}, {%0,%1,%2,%3};"
        : "+f"(d[0]), "+f"(d[1]), "+f"(d[2]), "+f"(d[3])
        : "r"(a[0]), "r"(a[1]), "r"(a[2]), "r"(a[3]), "r"(b[0]), "r"(b[1]));
}

__device__ __forceinline__ void cpa16(uint32_t smem, const void* g) {
    asm volatile("cp.async.cg.shared.global [%0], [%1], 16;" :: "r"(smem), "l"(g));
}
__device__ __forceinline__ void cpa_commit() { asm volatile("cp.async.commit_group;"); }
__device__ __forceinline__ void cpa_wait1()  { asm volatile("cp.async.wait_group 1;"); }

// ---------------- K1: build_act + W1T + b2 (merged) ----------------
__device__ __forceinline__ float knot(int j) { return -1.0f + 0.4f * (float)(j - 3); }

#define NB_ACT (BMAX * INDIM / 256)                 // 8192 (B=16384)
#define NB_W1T ((HID * KACT + 255) / 256)           // 4608
#define NB_B2  ((NOUT2 + 255) / 256)                // 33

__global__ __launch_bounds__(256) void k1_prep(const float* __restrict__ state,
                                               const float* __restrict__ novelU,
                                               const float* __restrict__ scale_base,
                                               const float* __restrict__ scale_sp,
                                               const float* __restrict__ coef,
                                               const float* __restrict__ f_b,
                                               const float* __restrict__ bias_b,
                                               int nbAct, int B) {
    int bx = blockIdx.x, tid = threadIdx.x;
    if (bx < nbAct) {
        int idx = bx * 256 + tid;
        if (idx >= B * INDIM) return;
        int b = idx / INDIM, i = idx - b * INDIM;
        float x = (i < STATE) ? state[b * STATE + i] : novelU[b * (INDIM - STATE) + (i - STATE)];
        g_x[b * INDIM + i] = x;
        g_act[(size_t)b * KACT + i] = __float2half(x / (1.0f + expf(-x)));
        float bb[11];
#pragma unroll
        for (int j = 0; j < 11; j++)
            bb[j] = (x >= knot(j) && x < knot(j + 1)) ? 1.0f : 0.0f;
#pragma unroll
        for (int ord = 1; ord <= 3; ord++) {
#pragma unroll
            for (int j = 0; j < 11 - 1; j++) {
                if (j >= 11 - ord) break;
                float l = (x - knot(j)) / (knot(j + ord) - knot(j));
                float r = (knot(j + ord + 1) - x) / (knot(j + ord + 1) - knot(j + 1));
                bb[j] = l * bb[j] + r * bb[j + 1];
            }
        }
        __half2 h0 = __floats2half2_rn(bb[0], bb[1]);
        __half2 h1 = __floats2half2_rn(bb[2], bb[3]);
        __half2 h2 = __floats2half2_rn(bb[4], bb[5]);
        __half2 h3 = __floats2half2_rn(bb[6], bb[7]);
        uint4 pack = make_uint4(*(uint32_t*)&h0, *(uint32_t*)&h1, *(uint32_t*)&h2, *(uint32_t*)&h3);
        *(uint4*)&g_act[(size_t)b * KACT + INDIM + i * NB] = pack;
    } else if (bx < nbAct + NB_W1T) {
        int idx = (bx - nbAct) * 256 + tid;
        if (idx >= HID * KACT) return;
        int o = idx / KACT, k = idx - o * KACT;
        float v;
        if (k < INDIM) {
            v = scale_base[k * HID + o];
        } else {
            int kk = k - INDIM;
            int i = kk >> 3, c = kk & 7;
            v = scale_sp[i * HID + o] * coef[(i * HID + o) * NB + c];
        }
        g_W1T[idx] = __float2half(v);
    } else {
        int idx = (bx - nbAct - NB_W1T) * 256 + tid;
        if (idx >= NOUT2) return;
        g_b2[idx] = (idx < 8192) ? f_b[idx] : bias_b[idx - 8192];
    }
}

// ---------------- GEMM body (R7 config: 512 thr, 128x256, KC=64, 3-stage) ---
#define KC    64
#define SAH   72
#define STG_H ((128 + 256) * SAH)
#define STGB  (STG_H * 2)
#define XSP   130

template<int K, bool EPI2>
__device__ __forceinline__ void gemm_body(const __half* __restrict__ A,
                                          const __half* __restrict__ Bt,
                                          __half* __restrict__ C,
                                          float* __restrict__ outAB,
                                          float* __restrict__ outBias,
                                          float* __restrict__ outO,
                                          char* dynsmem, int row0, int col0) {
    uint32_t smem_addr = (uint32_t)__cvta_generic_to_shared(dynsmem);

    int tid = threadIdx.x;
    int lane = tid & 31, wid = tid >> 5;
    int m0w = (wid & 1) * 64;
    int n0w = (wid >> 1) * 32;

    int rowA = lane & 15;
    int kAh  = 8 * (lane >> 4);
    int rowB = (lane & 7) + 8 * (lane >> 4);
    int kBh  = 8 * ((lane >> 3) & 1);

    float acc[4][4][4];
#pragma unroll
    for (int mt = 0; mt < 4; mt++)
#pragma unroll
        for (int nt = 0; nt < 4; nt++)
#pragma unroll
            for (int j = 0; j < 4; j++) acc[mt][nt][j] = 0.0f;

    const int nk = K / KC;

    auto load_stage = [&](int stg, int k0) {
        uint32_t base = smem_addr + stg * STGB;
#pragma unroll
        for (int c = 0; c < 6; c++) {
            int ch  = tid + c * 512;
            int r   = ch >> 3;
            int off = (ch & 7) * 8;
            const __half* src = (r < 128)
                ? A  + (size_t)(row0 + r) * K + k0 + off
                : Bt + (size_t)(col0 + (r - 128)) * K + k0 + off;
            cpa16(base + (uint32_t)(r * SAH + off) * 2, src);
        }
    };

    load_stage(0, 0);
    cpa_commit();
    load_stage(1, KC);
    cpa_commit();

    for (int it = 0; it < nk; it++) {
        int cur = it % 3;
        cpa_wait1();
        __syncthreads();
        int nx = it + 2;
        if (nx < nk) load_stage(nx % 3, nx * KC);
        cpa_commit();

        uint32_t sA = smem_addr + cur * STGB;
        uint32_t sB = sA + 128 * SAH * 2;
#pragma unroll
        for (int ks = 0; ks < 4; ks++) {
            int kh = ks * 16;
            uint32_t a[4][4], b[2][4];
#pragma unroll
            for (int mt = 0; mt < 4; mt++) {
                uint32_t addr = sA + (uint32_t)((m0w + mt * 16 + rowA) * SAH + kh + kAh) * 2;
                ldsm4(addr, a[mt][0], a[mt][1], a[mt][2], a[mt][3]);
            }
#pragma unroll
            for (int ng = 0; ng < 2; ng++) {
                uint32_t addr = sB + (uint32_t)((n0w + ng * 16 + rowB) * SAH + kh + kBh) * 2;
                ldsm4(addr, b[ng][0], b[ng][1], b[ng][2], b[ng][3]);
            }
#pragma unroll
            for (int mt = 0; mt < 4; mt++)
#pragma unroll
                for (int nt = 0; nt < 4; nt++)
                    mma_f16(acc[mt][nt], a[mt], &b[nt >> 1][(nt & 1) * 2]);
        }
    }

    int gid = lane >> 2, tig = lane & 3;

#pragma unroll
    for (int mt = 0; mt < 4; mt++) {
#pragma unroll
        for (int nt = 0; nt < 4; nt++) {
            int r0r = row0 + m0w + mt * 16 + gid;
            int n   = col0 + n0w + nt * 8 + 2 * tig;
            if (!EPI2) {
                __half2 v01 = __floats2half2_rn(acc[mt][nt][0], acc[mt][nt][1]);
                __half2 v23 = __floats2half2_rn(acc[mt][nt][2], acc[mt][nt][3]);
                *(__half2*)(C + (size_t)r0r * HID + n)       = v01;
                *(__half2*)(C + (size_t)(r0r + 8) * HID + n) = v23;
            } else {
                if (n >= NOUT2) continue;
                float b0 = g_b2[n], b1 = g_b2[n + 1];
                float2 v01 = make_float2(acc[mt][nt][0] + b0, acc[mt][nt][1] + b1);
                float2 v23 = make_float2(acc[mt][nt][2] + b0, acc[mt][nt][3] + b1);
                if (n < 8192) {
                    *(float2*)(outAB + (size_t)r0r * 8192 + n)       = v01;
                    *(float2*)(outAB + (size_t)(r0r + 8) * 8192 + n) = v23;
                } else {
                    int nb = n - 8192;
                    *(float2*)(outBias + (size_t)r0r * 64 + nb)       = v01;
                    *(float2*)(outBias + (size_t)(r0r + 8) * 64 + nb) = v23;
                }
            }
        }
    }

    if (EPI2 && col0 < 8192) {
        float* xs  = (float*)dynsmem;
        float* red = xs + 128 * XSP;
        __syncthreads();
        for (int i = tid * 4; i < 128 * 128; i += 512 * 4) {
            int r = i >> 7, u = i & 127;
            float4 v = *(const float4*)(g_x + (size_t)(row0 + r) * INDIM + u);
            xs[r * XSP + u]     = v.x;
            xs[r * XSP + u + 1] = v.y;
            xs[r * XSP + u + 2] = v.z;
            xs[r * XSP + u + 3] = v.w;
        }
        __syncthreads();

        int g = wid >> 1;
        int sl = g >> 2;
        int jj = g & 3;
#pragma unroll
        for (int mt = 0; mt < 4; mt++) {
            int lr = m0w + mt * 16 + gid;
            float p0 = 0.0f, p1 = 0.0f;
#pragma unroll
            for (int nt = 0; nt < 4; nt++) {
                int u  = n0w + nt * 8 + 2 * tig;
                int ux = u & 127;
                float n_b0 = g_b2[col0 + u], n_b1 = g_b2[col0 + u + 1];
                float x00 = xs[lr * XSP + ux],       x01 = xs[lr * XSP + ux + 1];
                float x10 = xs[(lr + 8) * XSP + ux], x11 = xs[(lr + 8) * XSP + ux + 1];
                p0 = fmaf(acc[mt][nt][0] + n_b0, x00, p0);
                p0 = fmaf(acc[mt][nt][1] + n_b1, x01, p0);
                p1 = fmaf(acc[mt][nt][2] + n_b0, x10, p1);
                p1 = fmaf(acc[mt][nt][3] + n_b1, x11, p1);
            }
            p0 += __shfl_xor_sync(0xffffffff, p0, 1);
            p0 += __shfl_xor_sync(0xffffffff, p0, 2);
            p1 += __shfl_xor_sync(0xffffffff, p1, 1);
            p1 += __shfl_xor_sync(0xffffffff, p1, 2);
            if (tig == 0) {
                red[(jj * 2 + sl) * 128 + lr]     = p0;
                red[(jj * 2 + sl) * 128 + lr + 8] = p1;
            }
        }
        __syncthreads();
        if (tid < 256) {
            int srow = tid & 127, s_l = tid >> 7;
            float v = red[(0 * 2 + s_l) * 128 + srow] + red[(1 * 2 + s_l) * 128 + srow]
                    + red[(2 * 2 + s_l) * 128 + srow] + red[(3 * 2 + s_l) * 128 + srow];
            outO[(size_t)(row0 + srow) * 64 + (col0 >> 7) + s_l] = v;
        }
    }
}

// ---------------- K2: gemm1 CTAs + W2T transpose CTAs (overlapped) ----------
#define NPREPB 512
#define NTILES ((NOUT2P / 32) * (HID / 32))   // 8448

__global__ __launch_bounds__(512) void k2_gemm1_prep(int g1n,
                                                     const float* __restrict__ f_w,
                                                     const float* __restrict__ bias_w) {
    extern __shared__ char dynsmem[];
    int bx = blockIdx.x, tid = threadIdx.x;
    if (bx < g1n) {
        int colT = bx & 3;            // HID/256 = 4
        int rowT = bx >> 2;
        gemm_body<KACT, false>(g_act, g_W1T, g_kan, nullptr, nullptr, nullptr,
                               dynsmem, rowT * 128, colT * 256);
    } else {
        float* tile = (float*)dynsmem;   // [32][33]
        int tx = tid & 31, ty0 = tid >> 5;   // 16 rows/pass, 2 passes
        for (int t = bx - g1n; t < NTILES; t += NPREPB) {
            int n0 = (t % (NOUT2P / 32)) * 32, h0 = (t / (NOUT2P / 32)) * 32;
            __syncthreads();
#pragma unroll
            for (int p = 0; p < 2; p++) {
                int ty = ty0 + p * 16;
                int n = n0 + tx;
                float v = 0.0f;
                if (n < 8192)       v = f_w[(size_t)(h0 + ty) * 8192 + n];
                else if (n < NOUT2) v = bias_w[(h0 + ty) * 64 + (n - 8192)];
                tile[ty * 33 + tx] = v;
            }
            __syncthreads();
#pragma unroll
            for (int p = 0; p < 2; p++) {
                int ty = ty0 + p * 16;
                g_W2T[(size_t)(n0 + ty) * HID + h0 + tx] = __float2half(tile[tx * 33 + ty]);
            }
        }
    }
}

// ---------------- gemm2 ----------------
__global__ __launch_bounds__(512) void mma_gemm2(float* __restrict__ outAB,
                                                 float* __restrict__ outBias,
                                                 float* __restrict__ outO) {
    extern __shared__ char dynsmem[];
    gemm_body<HID, true>(g_kan, g_W2T, nullptr, outAB, outBias, outO,
                         dynsmem, blockIdx.y * 128, blockIdx.x * 256);
}

// ---------------- out += bias ----------------
__global__ void add_bias(const float* __restrict__ biasOut, float* __restrict__ outO, int n) {
    int i = blockIdx.x * blockDim.x + threadIdx.x;
    if (i < n) outO[i] += biasOut[i];
}

// ---------------- launch ----------------
extern "C" void kernel_launch(void* const* d_in, const int* in_sizes, int n_in,
                              void* d_out, int out_size) {
    const float* novelU     = (const float*)d_in[0];
    const float* state      = (const float*)d_in[1];
    const float* coef       = (const float*)d_in[2];
    const float* scale_base = (const float*)d_in[3];
    const float* scale_sp   = (const float*)d_in[4];
    const float* bias_w     = (const float*)d_in[5];
    const float* bias_b     = (const float*)d_in[6];
    const float* f_w        = (const float*)d_in[7];
    const float* f_b        = (const float*)d_in[8];
    float* out = (float*)d_out;

    int B = in_sizes[0] / 64;
    if (B > BMAX) B = BMAX;

    float* outO    = out;
    float* outAB   = out + (size_t)B * 64;
    float* outBias = out + (size_t)B * 64 + (size_t)B * 8192;

    const int smem_stage = 3 * STGB;
    const int smem_epi   = 128 * XSP * 4 + 8 * 128 * 4;
    const int smem_bytes = smem_epi > smem_stage ? smem_epi : smem_stage;
    static bool attr_set = false;
    if (!attr_set) {
        cudaFuncSetAttribute(k2_gemm1_prep,
                             cudaFuncAttributeMaxDynamicSharedMemorySize, smem_bytes);
        cudaFuncSetAttribute(mma_gemm2,
                             cudaFuncAttributeMaxDynamicSharedMemorySize, smem_bytes);
        attr_set = true;
    }

    int nbAct = (B * INDIM + 255) / 256;
    k1_prep<<<nbAct + NB_W1T + NB_B2, 256>>>(state, novelU, scale_base, scale_sp,
                                             coef, f_b, bias_b, nbAct, B);

    int g1n = (HID / 256) * (B / 128);
    k2_gemm1_prep<<<g1n + NPREPB, 512, smem_bytes>>>(g1n, f_w, bias_w);

    dim3 g2(NOUT2P / 256, B / 128);
    mma_gemm2<<<g2, 512, smem_bytes>>>(outAB, outBias, outO);

    add_bias<<<(B * 64 + 255) / 256, 256>>>(outBias, outO, B * 64);
}

// round 11
// speedup vs baseline: 1.0468x; 1.0044x over previous
#include <cuda_runtime.h>
#include <cuda_fp16.h>
#include <math.h>
#include <stdint.h>

// Problem constants
#define BMAX   16384
#define INDIM  128
#define STATE  64
#define HID    1024
#define NB     8
#define KACT   (INDIM + INDIM * NB)   // 1152
#define NOUT2  (8192 + 64)            // 8256
#define NOUT2P 8448                   // padded to multiple of 256

// ---------------- scratch ----------------
__device__ float  g_x   [BMAX * INDIM];
__device__ __half g_act [BMAX * KACT];            // [b][k]  (A1, K-major)
__device__ __half g_kan [BMAX * HID];             // [b][h]  (A2, K-major)
__device__ __half g_W1k [KACT * HID];             // [k][o]  (B1, k-row major)
__device__ __half g_W2h [(size_t)HID * NOUT2P];   // [h][n]  (B2, k-row major)
__device__ float  g_b2  [NOUT2];

// ---------------- helpers ----------------
__device__ __forceinline__ void ldsm4(uint32_t addr, uint32_t& r0, uint32_t& r1,
                                      uint32_t& r2, uint32_t& r3) {
    asm volatile("ldmatrix.sync.aligned.m8n8.x4.shared.b16 {%0,%1,%2,%3}, [%4];"
                 : "=r"(r0), "=r"(r1), "=r"(r2), "=r"(r3) : "r"(addr));
}
__device__ __forceinline__ void ldsm4t(uint32_t addr, uint32_t& r0, uint32_t& r1,
                                       uint32_t& r2, uint32_t& r3) {
    asm volatile("ldmatrix.sync.aligned.m8n8.x4.trans.shared.b16 {%0,%1,%2,%3}, [%4];"
                 : "=r"(r0), "=r"(r1), "=r"(r2), "=r"(r3) : "r"(addr));
}

__device__ __forceinline__ void mma_f16(float* d, const uint32_t* a, const uint32_t* b) {
    asm volatile(
        "mma.sync.aligned.m16n8k16.row.col.f32.f16.f16.f32 "
        "{%0,%1,%2,%3}, {%4,%5,%6,%7}, {%8,%9}, {%0,%1,%2,%3};"
        : "+f"(d[0]), "+f"(d[1]), "+f"(d[2]), "+f"(d[3])
        : "r"(a[0]), "r"(a[1]), "r"(a[2]), "r"(a[3]), "r"(b[0]), "r"(b[1]));
}

__device__ __forceinline__ void cpa16(uint32_t smem, const void* g) {
    asm volatile("cp.async.cg.shared.global [%0], [%1], 16;" :: "r"(smem), "l"(g));
}
__device__ __forceinline__ void cpa_commit() { asm volatile("cp.async.commit_group;"); }
__device__ __forceinline__ void cpa_wait1()  { asm volatile("cp.async.wait_group 1;"); }

// ---------------- K1: build_act + W1k + W2h + b2 (merged, all coalesced) ----
__device__ __forceinline__ float knot(int j) { return -1.0f + 0.4f * (float)(j - 3); }

#define NB_W1  ((KACT * HID + 255) / 256)               // 4608
#define NB_W2  (((int)((size_t)HID * NOUT2P) + 255) / 256)  // 33792
#define NB_B2  ((NOUT2 + 255) / 256)                    // 33

__global__ __launch_bounds__(256) void k1_prep(const float* __restrict__ state,
                                               const float* __restrict__ novelU,
                                               const float* __restrict__ scale_base,
                                               const float* __restrict__ scale_sp,
                                               const float* __restrict__ coef,
                                               const float* __restrict__ f_w,
                                               const float* __restrict__ bias_w,
                                               const float* __restrict__ f_b,
                                               const float* __restrict__ bias_b,
                                               int nbAct, int B) {
    int bx = blockIdx.x, tid = threadIdx.x;
    if (bx < nbAct) {
        int idx = bx * 256 + tid;
        if (idx >= B * INDIM) return;
        int b = idx / INDIM, i = idx - b * INDIM;
        float x = (i < STATE) ? state[b * STATE + i] : novelU[b * (INDIM - STATE) + (i - STATE)];
        g_x[b * INDIM + i] = x;
        g_act[(size_t)b * KACT + i] = __float2half(__fdividef(x, 1.0f + __expf(-x)));
        float bb[11];
#pragma unroll
        for (int j = 0; j < 11; j++)
            bb[j] = (x >= knot(j) && x < knot(j + 1)) ? 1.0f : 0.0f;
#pragma unroll
        for (int ord = 1; ord <= 3; ord++) {
#pragma unroll
            for (int j = 0; j < 11 - 1; j++) {
                if (j >= 11 - ord) break;
                float l = (x - knot(j)) / (knot(j + ord) - knot(j));
                float r = (knot(j + ord + 1) - x) / (knot(j + ord + 1) - knot(j + 1));
                bb[j] = l * bb[j] + r * bb[j + 1];
            }
        }
        __half2 h0 = __floats2half2_rn(bb[0], bb[1]);
        __half2 h1 = __floats2half2_rn(bb[2], bb[3]);
        __half2 h2 = __floats2half2_rn(bb[4], bb[5]);
        __half2 h3 = __floats2half2_rn(bb[6], bb[7]);
        uint4 pack = make_uint4(*(uint32_t*)&h0, *(uint32_t*)&h1, *(uint32_t*)&h2, *(uint32_t*)&h3);
        *(uint4*)&g_act[(size_t)b * KACT + INDIM + i * NB] = pack;
    } else if (bx < nbAct + NB_W1) {
        int idx = (bx - nbAct) * 256 + tid;
        if (idx >= KACT * HID) return;
        int k = idx / HID, o = idx - k * HID;
        float v;
        if (k < INDIM) {
            v = scale_base[k * HID + o];           // coalesced in o
        } else {
            int kk = k - INDIM;
            int i = kk >> 3, c = kk & 7;
            v = scale_sp[i * HID + o] * coef[(i * HID + o) * NB + c];
        }
        g_W1k[idx] = __float2half(v);
    } else if (bx < nbAct + NB_W1 + NB_W2) {
        size_t idx = (size_t)(bx - nbAct - NB_W1) * 256 + tid;
        if (idx >= (size_t)HID * NOUT2P) return;
        int h = (int)(idx / NOUT2P), n = (int)(idx % NOUT2P);
        float v = 0.0f;
        if (n < 8192)       v = f_w[(size_t)h * 8192 + n];     // coalesced in n
        else if (n < NOUT2) v = bias_w[h * 64 + (n - 8192)];
        g_W2h[idx] = __float2half(v);
    } else {
        int idx = (bx - nbAct - NB_W1 - NB_W2) * 256 + tid;
        if (idx >= NOUT2) return;
        g_b2[idx] = (idx < 8192) ? f_b[idx] : bias_b[idx - 8192];
    }
}

// ---------------- FP16 tensor-core GEMM (trans-B) ---------------------------
// CTA tile 128x256, 512 threads (16 warps, warp tile 64x32), KC=64, 3-stage.
// A smem: [128 m][72 halves]; B smem: [64 k][264 halves] (trans ldmatrix).
#define KC    64
#define SAH   72
#define SBN   264
#define A_ST  (128 * SAH * 2)          // 18432
#define B_ST  (KC * SBN * 2)           // 33792
#define STGB  (A_ST + B_ST)            // 52224
#define XSP   130

template<int K, int NBSTR, bool EPI2>
__device__ __forceinline__ void gemm_body(const __half* __restrict__ A,
                                          const __half* __restrict__ Bg,
                                          __half* __restrict__ C,
                                          float* __restrict__ outAB,
                                          float* __restrict__ outBias,
                                          float* __restrict__ outO,
                                          char* dynsmem, int row0, int col0) {
    uint32_t smem_addr = (uint32_t)__cvta_generic_to_shared(dynsmem);

    int tid = threadIdx.x;
    int lane = tid & 31, wid = tid >> 5;
    int m0w = (wid & 1) * 64;
    int n0w = (wid >> 1) * 32;

    // A fragment addressing (non-trans, [m][k] smem)
    int rowA = lane & 15;
    int kAh  = 8 * (lane >> 4);
    // B fragment addressing (trans, [k][n] smem)
    int krowB = (lane & 7) + 8 * ((lane >> 3) & 1);
    int ncolB = 8 * (lane >> 4);

    float acc[4][4][4];
#pragma unroll
    for (int mt = 0; mt < 4; mt++)
#pragma unroll
        for (int nt = 0; nt < 4; nt++)
#pragma unroll
            for (int j = 0; j < 4; j++) acc[mt][nt][j] = 0.0f;

    const int nk = K / KC;

    auto load_stage = [&](int stg, int k0) {
        uint32_t base = smem_addr + stg * STGB;
#pragma unroll
        for (int c = 0; c < 6; c++) {
            if (c < 2) {
                int ch = tid + c * 512;          // 0..1023 : A chunks
                int r = ch >> 3, off = (ch & 7) * 8;
                cpa16(base + (uint32_t)(r * SAH + off) * 2,
                      A + (size_t)(row0 + r) * K + k0 + off);
            } else {
                int ch = tid + (c - 2) * 512;    // 0..2047 : B chunks
                int r = ch >> 5, off = (ch & 31) * 8;
                cpa16(base + A_ST + (uint32_t)(r * SBN + off) * 2,
                      Bg + (size_t)(k0 + r) * NBSTR + col0 + off);
            }
        }
    };

    load_stage(0, 0);
    cpa_commit();
    load_stage(1, KC);
    cpa_commit();

    for (int it = 0; it < nk; it++) {
        int cur = it % 3;
        cpa_wait1();
        __syncthreads();
        int nx = it + 2;
        if (nx < nk) load_stage(nx % 3, nx * KC);
        cpa_commit();

        uint32_t sA = smem_addr + cur * STGB;
        uint32_t sB = sA + A_ST;
#pragma unroll
        for (int ks = 0; ks < 4; ks++) {
            int kh = ks * 16;
            uint32_t a[4][4], b[2][4];
#pragma unroll
            for (int mt = 0; mt < 4; mt++) {
                uint32_t addr = sA + (uint32_t)((m0w + mt * 16 + rowA) * SAH + kh + kAh) * 2;
                ldsm4(addr, a[mt][0], a[mt][1], a[mt][2], a[mt][3]);
            }
#pragma unroll
            for (int ng = 0; ng < 2; ng++) {
                uint32_t addr = sB + (uint32_t)((kh + krowB) * SBN + n0w + ng * 16 + ncolB) * 2;
                ldsm4t(addr, b[ng][0], b[ng][1], b[ng][2], b[ng][3]);
            }
#pragma unroll
            for (int mt = 0; mt < 4; mt++)
#pragma unroll
                for (int nt = 0; nt < 4; nt++)
                    mma_f16(acc[mt][nt], a[mt], &b[nt >> 1][(nt & 1) * 2]);
        }
    }

    int gid = lane >> 2, tig = lane & 3;

#pragma unroll
    for (int mt = 0; mt < 4; mt++) {
#pragma unroll
        for (int nt = 0; nt < 4; nt++) {
            int r0r = row0 + m0w + mt * 16 + gid;
            int n   = col0 + n0w + nt * 8 + 2 * tig;
            if (!EPI2) {
                __half2 v01 = __floats2half2_rn(acc[mt][nt][0], acc[mt][nt][1]);
                __half2 v23 = __floats2half2_rn(acc[mt][nt][2], acc[mt][nt][3]);
                *(__half2*)(C + (size_t)r0r * HID + n)       = v01;
                *(__half2*)(C + (size_t)(r0r + 8) * HID + n) = v23;
            } else {
                if (n >= NOUT2) continue;
                float b0 = g_b2[n], b1 = g_b2[n + 1];
                float2 v01 = make_float2(acc[mt][nt][0] + b0, acc[mt][nt][1] + b1);
                float2 v23 = make_float2(acc[mt][nt][2] + b0, acc[mt][nt][3] + b1);
                if (n < 8192) {
                    *(float2*)(outAB + (size_t)r0r * 8192 + n)       = v01;
                    *(float2*)(outAB + (size_t)(r0r + 8) * 8192 + n) = v23;
                } else {
                    int nb = n - 8192;
                    *(float2*)(outBias + (size_t)r0r * 64 + nb)       = v01;
                    *(float2*)(outBias + (size_t)(r0r + 8) * 64 + nb) = v23;
                }
            }
        }
    }

    if (EPI2 && col0 < 8192) {
        float* xs  = (float*)dynsmem;
        float* red = xs + 128 * XSP;
        __syncthreads();
        for (int i = tid * 4; i < 128 * 128; i += 512 * 4) {
            int r = i >> 7, u = i & 127;
            float4 v = *(const float4*)(g_x + (size_t)(row0 + r) * INDIM + u);
            xs[r * XSP + u]     = v.x;
            xs[r * XSP + u + 1] = v.y;
            xs[r * XSP + u + 2] = v.z;
            xs[r * XSP + u + 3] = v.w;
        }
        __syncthreads();

        int g = wid >> 1;
        int sl = g >> 2;
        int jj = g & 3;
#pragma unroll
        for (int mt = 0; mt < 4; mt++) {
            int lr = m0w + mt * 16 + gid;
            float p0 = 0.0f, p1 = 0.0f;
#pragma unroll
            for (int nt = 0; nt < 4; nt++) {
                int u  = n0w + nt * 8 + 2 * tig;
                int ux = u & 127;
                float n_b0 = g_b2[col0 + u], n_b1 = g_b2[col0 + u + 1];
                float x00 = xs[lr * XSP + ux],       x01 = xs[lr * XSP + ux + 1];
                float x10 = xs[(lr + 8) * XSP + ux], x11 = xs[(lr + 8) * XSP + ux + 1];
                p0 = fmaf(acc[mt][nt][0] + n_b0, x00, p0);
                p0 = fmaf(acc[mt][nt][1] + n_b1, x01, p0);
                p1 = fmaf(acc[mt][nt][2] + n_b0, x10, p1);
                p1 = fmaf(acc[mt][nt][3] + n_b1, x11, p1);
            }
            p0 += __shfl_xor_sync(0xffffffff, p0, 1);
            p0 += __shfl_xor_sync(0xffffffff, p0, 2);
            p1 += __shfl_xor_sync(0xffffffff, p1, 1);
            p1 += __shfl_xor_sync(0xffffffff, p1, 2);
            if (tig == 0) {
                red[(jj * 2 + sl) * 128 + lr]     = p0;
                red[(jj * 2 + sl) * 128 + lr + 8] = p1;
            }
        }
        __syncthreads();
        if (tid < 256) {
            int srow = tid & 127, s_l = tid >> 7;
            float v = red[(0 * 2 + s_l) * 128 + srow] + red[(1 * 2 + s_l) * 128 + srow]
                    + red[(2 * 2 + s_l) * 128 + srow] + red[(3 * 2 + s_l) * 128 + srow];
            outO[(size_t)(row0 + srow) * 64 + (col0 >> 7) + s_l] = v;
        }
    }
}

__global__ __launch_bounds__(512) void mma_gemm1() {
    extern __shared__ char dynsmem[];
    gemm_body<KACT, HID, false>(g_act, g_W1k, g_kan, nullptr, nullptr, nullptr,
                                dynsmem, blockIdx.y * 128, blockIdx.x * 256);
}

__global__ __launch_bounds__(512) void mma_gemm2(float* __restrict__ outAB,
                                                 float* __restrict__ outBias,
                                                 float* __restrict__ outO) {
    extern __shared__ char dynsmem[];
    gemm_body<HID, NOUT2P, true>(g_kan, g_W2h, nullptr, outAB, outBias, outO,
                                 dynsmem, blockIdx.y * 128, blockIdx.x * 256);
}

// ---------------- out += bias ----------------
__global__ void add_bias(const float* __restrict__ biasOut, float* __restrict__ outO, int n) {
    int i = blockIdx.x * blockDim.x + threadIdx.x;
    if (i < n) outO[i] += biasOut[i];
}

// ---------------- launch ----------------
extern "C" void kernel_launch(void* const* d_in, const int* in_sizes, int n_in,
                              void* d_out, int out_size) {
    const float* novelU     = (const float*)d_in[0];
    const float* state      = (const float*)d_in[1];
    const float* coef       = (const float*)d_in[2];
    const float* scale_base = (const float*)d_in[3];
    const float* scale_sp   = (const float*)d_in[4];
    const float* bias_w     = (const float*)d_in[5];
    const float* bias_b     = (const float*)d_in[6];
    const float* f_w        = (const float*)d_in[7];
    const float* f_b        = (const float*)d_in[8];
    float* out = (float*)d_out;

    int B = in_sizes[0] / 64;
    if (B > BMAX) B = BMAX;

    float* outO    = out;
    float* outAB   = out + (size_t)B * 64;
    float* outBias = out + (size_t)B * 64 + (size_t)B * 8192;

    const int smem_stage = 3 * STGB;                    // 156672
    const int smem_epi   = 128 * XSP * 4 + 8 * 128 * 4; // 70656
    const int smem_bytes = smem_epi > smem_stage ? smem_epi : smem_stage;
    static bool attr_set = false;
    if (!attr_set) {
        cudaFuncSetAttribute(mma_gemm1,
                             cudaFuncAttributeMaxDynamicSharedMemorySize, smem_bytes);
        cudaFuncSetAttribute(mma_gemm2,
                             cudaFuncAttributeMaxDynamicSharedMemorySize, smem_bytes);
        attr_set = true;
    }

    int nbAct = (B * INDIM + 255) / 256;
    k1_prep<<<nbAct + NB_W1 + NB_W2 + NB_B2, 256>>>(state, novelU, scale_base, scale_sp,
                                                    coef, f_w, bias_w, f_b, bias_b,
                                                    nbAct, B);

    dim3 g1(HID / 256, B / 128);
    mma_gemm1<<<g1, 512, smem_bytes>>>();

    dim3 g2(NOUT2P / 256, B / 128);
    mma_gemm2<<<g2, 512, smem_bytes>>>(outAB, outBias, outO);

    add_bias<<<(B * 64 + 255) / 256, 256>>>(outBias, outO, B * 64);
}

// round 12
// speedup vs baseline: 1.1892x; 1.1360x over previous
#include <cuda_runtime.h>
#include <cuda_fp16.h>
#include <math.h>
#include <stdint.h>

// Problem constants
#define BMAX   16384
#define INDIM  128
#define STATE  64
#define HID    1024
#define NB     8
#define KACT   (INDIM + INDIM * NB)   // 1152
#define NOUT2  (8192 + 64)            // 8256
#define NOUT2P 8320                   // padded to multiple of 128

// ---------------- scratch ----------------
__device__ float  g_x   [BMAX * INDIM];
__device__ __half g_act [BMAX * KACT];            // [b][k]
__device__ __half g_kan [BMAX * HID];             // [b][h]
__device__ __half g_W1k [KACT * HID];             // [k][o]  k-row major
__device__ __half g_W2h [(size_t)HID * NOUT2P];   // [h][n]  k-row major
__device__ float  g_b2  [NOUT2];

// ---------------- helpers ----------------
__device__ __forceinline__ void ldsm4(uint32_t addr, uint32_t& r0, uint32_t& r1,
                                      uint32_t& r2, uint32_t& r3) {
    asm volatile("ldmatrix.sync.aligned.m8n8.x4.shared.b16 {%0,%1,%2,%3}, [%4];"
                 : "=r"(r0), "=r"(r1), "=r"(r2), "=r"(r3) : "r"(addr));
}
__device__ __forceinline__ void ldsm4t(uint32_t addr, uint32_t& r0, uint32_t& r1,
                                       uint32_t& r2, uint32_t& r3) {
    asm volatile("ldmatrix.sync.aligned.m8n8.x4.trans.shared.b16 {%0,%1,%2,%3}, [%4];"
                 : "=r"(r0), "=r"(r1), "=r"(r2), "=r"(r3) : "r"(addr));
}

__device__ __forceinline__ void mma_f16(float* d, const uint32_t* a, const uint32_t* b) {
    asm volatile(
        "mma.sync.aligned.m16n8k16.row.col.f32.f16.f16.f32 "
        "{%0,%1,%2,%3}, {%4,%5,%6,%7}, {%8,%9}, {%0,%1,%2,%3};"
        : "+f"(d[0]), "+f"(d[1]), "+f"(d[2]), "+f"(d[3])
        : "r"(a[0]), "r"(a[1]), "r"(a[2]), "r"(a[3]), "r"(b[0]), "r"(b[1]));
}

__device__ __forceinline__ void cpa16(uint32_t smem, const void* g) {
    asm volatile("cp.async.cg.shared.global [%0], [%1], 16;" :: "r"(smem), "l"(g));
}
__device__ __forceinline__ void cpa_commit() { asm volatile("cp.async.commit_group;"); }
__device__ __forceinline__ void cpa_wait1()  { asm volatile("cp.async.wait_group 1;"); }

// ---------------- K1: build_act + W1k + W2h + b2 (merged) ----
__device__ __forceinline__ float knot(int j) { return -1.0f + 0.4f * (float)(j - 3); }

#define NB_W1  ((KACT * HID + 255) / 256)
#define NB_W2  (((int)((size_t)HID * NOUT2P) + 255) / 256)
#define NB_B2  ((NOUT2 + 255) / 256)

__global__ __launch_bounds__(256) void k1_prep(const float* __restrict__ state,
                                               const float* __restrict__ novelU,
                                               const float* __restrict__ scale_base,
                                               const float* __restrict__ scale_sp,
                                               const float* __restrict__ coef,
                                               const float* __restrict__ f_w,
                                               const float* __restrict__ bias_w,
                                               const float* __restrict__ f_b,
                                               const float* __restrict__ bias_b,
                                               int nbAct, int B) {
    int bx = blockIdx.x, tid = threadIdx.x;
    if (bx < nbAct) {
        int idx = bx * 256 + tid;
        if (idx >= B * INDIM) return;
        int b = idx / INDIM, i = idx - b * INDIM;
        float x = (i < STATE) ? state[b * STATE + i] : novelU[b * (INDIM - STATE) + (i - STATE)];
        g_x[b * INDIM + i] = x;
        g_act[(size_t)b * KACT + i] = __float2half(__fdividef(x, 1.0f + __expf(-x)));
        float bb[11];
#pragma unroll
        for (int j = 0; j < 11; j++)
            bb[j] = (x >= knot(j) && x < knot(j + 1)) ? 1.0f : 0.0f;
#pragma unroll
        for (int ord = 1; ord <= 3; ord++) {
#pragma unroll
            for (int j = 0; j < 11 - 1; j++) {
                if (j >= 11 - ord) break;
                float l = (x - knot(j)) / (knot(j + ord) - knot(j));
                float r = (knot(j + ord + 1) - x) / (knot(j + ord + 1) - knot(j + 1));
                bb[j] = l * bb[j] + r * bb[j + 1];
            }
        }
        __half2 h0 = __floats2half2_rn(bb[0], bb[1]);
        __half2 h1 = __floats2half2_rn(bb[2], bb[3]);
        __half2 h2 = __floats2half2_rn(bb[4], bb[5]);
        __half2 h3 = __floats2half2_rn(bb[6], bb[7]);
        uint4 pack = make_uint4(*(uint32_t*)&h0, *(uint32_t*)&h1, *(uint32_t*)&h2, *(uint32_t*)&h3);
        *(uint4*)&g_act[(size_t)b * KACT + INDIM + i * NB] = pack;
    } else if (bx < nbAct + NB_W1) {
        int idx = (bx - nbAct) * 256 + tid;
        if (idx >= KACT * HID) return;
        int k = idx / HID, o = idx - k * HID;
        float v;
        if (k < INDIM) {
            v = scale_base[k * HID + o];
        } else {
            int kk = k - INDIM;
            int i = kk >> 3, c = kk & 7;
            v = scale_sp[i * HID + o] * coef[(i * HID + o) * NB + c];
        }
        g_W1k[idx] = __float2half(v);
    } else if (bx < nbAct + NB_W1 + NB_W2) {
        size_t idx = (size_t)(bx - nbAct - NB_W1) * 256 + tid;
        if (idx >= (size_t)HID * NOUT2P) return;
        int h = (int)(idx / NOUT2P), n = (int)(idx % NOUT2P);
        float v = 0.0f;
        if (n < 8192)       v = f_w[(size_t)h * 8192 + n];
        else if (n < NOUT2) v = bias_w[h * 64 + (n - 8192)];
        g_W2h[idx] = __float2half(v);
    } else {
        int idx = (bx - nbAct - NB_W1 - NB_W2) * 256 + tid;
        if (idx >= NOUT2) return;
        g_b2[idx] = (idx < 8192) ? f_b[idx] : bias_b[idx - 8192];
    }
}

// ---------------- FP16 tensor-core GEMM (trans-B, 2 CTAs/SM) ----------------
// CTA tile 128x128, 256 threads (8 warps 2x4, warp tile 64x32), KC=64, 3-stage.
#define KC    64
#define SAH   72                       // A smem stride (halves), 144 B
#define SBN   136                      // B smem stride (halves), 272 B (16 mod 128)
#define A_ST  (128 * SAH * 2)          // 18432
#define B_ST  (KC * SBN * 2)           // 17408
#define STGB  (A_ST + B_ST)            // 35840
#define XSP   130

template<int K, int NBSTR, bool EPI2>
__device__ __forceinline__ void gemm_body(const __half* __restrict__ A,
                                          const __half* __restrict__ Bg,
                                          __half* __restrict__ C,
                                          float* __restrict__ outAB,
                                          float* __restrict__ outBias,
                                          float* __restrict__ outO,
                                          char* dynsmem, int row0, int col0) {
    uint32_t smem_addr = (uint32_t)__cvta_generic_to_shared(dynsmem);

    int tid = threadIdx.x;
    int lane = tid & 31, wid = tid >> 5;          // 8 warps
    int m0w = (wid & 1) * 64;
    int n0w = (wid >> 1) * 32;                    // 4 n-groups x 32 = 128

    int rowA  = lane & 15;
    int kAh   = 8 * (lane >> 4);
    int krowB = (lane & 7) + 8 * ((lane >> 3) & 1);
    int ncolB = 8 * (lane >> 4);

    float acc[4][4][4];
#pragma unroll
    for (int mt = 0; mt < 4; mt++)
#pragma unroll
        for (int nt = 0; nt < 4; nt++)
#pragma unroll
            for (int j = 0; j < 4; j++) acc[mt][nt][j] = 0.0f;

    const int nk = K / KC;

    auto load_stage = [&](int stg, int k0) {
        uint32_t base = smem_addr + stg * STGB;
#pragma unroll
        for (int c = 0; c < 8; c++) {
            if (c < 4) {
                int ch = tid + c * 256;            // 0..1023 : A (128 rows x 8 chunks)
                int r = ch >> 3, off = (ch & 7) * 8;
                cpa16(base + (uint32_t)(r * SAH + off) * 2,
                      A + (size_t)(row0 + r) * K + k0 + off);
            } else {
                int ch = tid + (c - 4) * 256;      // 0..1023 : B (64 rows x 16 chunks)
                int r = ch >> 4, off = (ch & 15) * 8;
                cpa16(base + A_ST + (uint32_t)(r * SBN + off) * 2,
                      Bg + (size_t)(k0 + r) * NBSTR + col0 + off);
            }
        }
    };

    load_stage(0, 0);
    cpa_commit();
    load_stage(1, KC);
    cpa_commit();

    for (int it = 0; it < nk; it++) {
        int cur = it % 3;
        cpa_wait1();
        __syncthreads();
        int nx = it + 2;
        if (nx < nk) load_stage(nx % 3, nx * KC);
        cpa_commit();

        uint32_t sA = smem_addr + cur * STGB;
        uint32_t sB = sA + A_ST;
#pragma unroll
        for (int ks = 0; ks < 4; ks++) {
            int kh = ks * 16;
            uint32_t a[4][4], b[2][4];
#pragma unroll
            for (int mt = 0; mt < 4; mt++) {
                uint32_t addr = sA + (uint32_t)((m0w + mt * 16 + rowA) * SAH + kh + kAh) * 2;
                ldsm4(addr, a[mt][0], a[mt][1], a[mt][2], a[mt][3]);
            }
#pragma unroll
            for (int ng = 0; ng < 2; ng++) {
                uint32_t addr = sB + (uint32_t)((kh + krowB) * SBN + n0w + ng * 16 + ncolB) * 2;
                ldsm4t(addr, b[ng][0], b[ng][1], b[ng][2], b[ng][3]);
            }
#pragma unroll
            for (int mt = 0; mt < 4; mt++)
#pragma unroll
                for (int nt = 0; nt < 4; nt++)
                    mma_f16(acc[mt][nt], a[mt], &b[nt >> 1][(nt & 1) * 2]);
        }
    }

    int gid = lane >> 2, tig = lane & 3;

#pragma unroll
    for (int mt = 0; mt < 4; mt++) {
#pragma unroll
        for (int nt = 0; nt < 4; nt++) {
            int r0r = row0 + m0w + mt * 16 + gid;
            int n   = col0 + n0w + nt * 8 + 2 * tig;
            if (!EPI2) {
                __half2 v01 = __floats2half2_rn(acc[mt][nt][0], acc[mt][nt][1]);
                __half2 v23 = __floats2half2_rn(acc[mt][nt][2], acc[mt][nt][3]);
                *(__half2*)(C + (size_t)r0r * HID + n)       = v01;
                *(__half2*)(C + (size_t)(r0r + 8) * HID + n) = v23;
            } else {
                if (n >= NOUT2) continue;
                float b0 = g_b2[n], b1 = g_b2[n + 1];
                float2 v01 = make_float2(acc[mt][nt][0] + b0, acc[mt][nt][1] + b1);
                float2 v23 = make_float2(acc[mt][nt][2] + b0, acc[mt][nt][3] + b1);
                if (n < 8192) {
                    *(float2*)(outAB + (size_t)r0r * 8192 + n)       = v01;
                    *(float2*)(outAB + (size_t)(r0r + 8) * 8192 + n) = v23;
                } else {
                    int nb = n - 8192;
                    *(float2*)(outBias + (size_t)r0r * 64 + nb)       = v01;
                    *(float2*)(outBias + (size_t)(r0r + 8) * 64 + nb) = v23;
                }
            }
        }
    }

    // ---- fused out = (AB + f_b tile) . x ; 128-col tile = 1 s value ----
    if (EPI2 && col0 < 8192) {
        float* xs  = (float*)dynsmem;            // [128][XSP]
        float* red = xs + 128 * XSP;             // [4][128]
        __syncthreads();
        for (int i = tid * 4; i < 128 * 128; i += 256 * 4) {
            int r = i >> 7, u = i & 127;
            float4 v = *(const float4*)(g_x + (size_t)(row0 + r) * INDIM + u);
            xs[r * XSP + u]     = v.x;
            xs[r * XSP + u + 1] = v.y;
            xs[r * XSP + u + 2] = v.z;
            xs[r * XSP + u + 3] = v.w;
        }
        __syncthreads();

        int nw = wid >> 1;   // reduction slot 0..3
#pragma unroll
        for (int mt = 0; mt < 4; mt++) {
            int lr = m0w + mt * 16 + gid;
            float p0 = 0.0f, p1 = 0.0f;
#pragma unroll
            for (int nt = 0; nt < 4; nt++) {
                int u = n0w + nt * 8 + 2 * tig;      // 0..127
                float n_b0 = g_b2[col0 + u], n_b1 = g_b2[col0 + u + 1];
                float x00 = xs[lr * XSP + u],        x01 = xs[lr * XSP + u + 1];
                float x10 = xs[(lr + 8) * XSP + u],  x11 = xs[(lr + 8) * XSP + u + 1];
                p0 = fmaf(acc[mt][nt][0] + n_b0, x00, p0);
                p0 = fmaf(acc[mt][nt][1] + n_b1, x01, p0);
                p1 = fmaf(acc[mt][nt][2] + n_b0, x10, p1);
                p1 = fmaf(acc[mt][nt][3] + n_b1, x11, p1);
            }
            p0 += __shfl_xor_sync(0xffffffff, p0, 1);
            p0 += __shfl_xor_sync(0xffffffff, p0, 2);
            p1 += __shfl_xor_sync(0xffffffff, p1, 1);
            p1 += __shfl_xor_sync(0xffffffff, p1, 2);
            if (tig == 0) {
                red[nw * 128 + lr]     = p0;
                red[nw * 128 + lr + 8] = p1;
            }
        }
        __syncthreads();
        if (tid < 128) {
            float v = red[tid] + red[128 + tid] + red[256 + tid] + red[384 + tid];
            outO[(size_t)(row0 + tid) * 64 + (col0 >> 7)] = v;
        }
    }
}

__global__ __launch_bounds__(256, 2) void mma_gemm1() {
    extern __shared__ char dynsmem[];
    gemm_body<KACT, HID, false>(g_act, g_W1k, g_kan, nullptr, nullptr, nullptr,
                                dynsmem, blockIdx.y * 128, blockIdx.x * 128);
}

__global__ __launch_bounds__(256, 2) void mma_gemm2(float* __restrict__ outAB,
                                                    float* __restrict__ outBias,
                                                    float* __restrict__ outO) {
    extern __shared__ char dynsmem[];
    gemm_body<HID, NOUT2P, true>(g_kan, g_W2h, nullptr, outAB, outBias, outO,
                                 dynsmem, blockIdx.y * 128, blockIdx.x * 128);
}

// ---------------- out += bias ----------------
__global__ void add_bias(const float* __restrict__ biasOut, float* __restrict__ outO, int n) {
    int i = blockIdx.x * blockDim.x + threadIdx.x;
    if (i < n) outO[i] += biasOut[i];
}

// ---------------- launch ----------------
extern "C" void kernel_launch(void* const* d_in, const int* in_sizes, int n_in,
                              void* d_out, int out_size) {
    const float* novelU     = (const float*)d_in[0];
    const float* state      = (const float*)d_in[1];
    const float* coef       = (const float*)d_in[2];
    const float* scale_base = (const float*)d_in[3];
    const float* scale_sp   = (const float*)d_in[4];
    const float* bias_w     = (const float*)d_in[5];
    const float* bias_b     = (const float*)d_in[6];
    const float* f_w        = (const float*)d_in[7];
    const float* f_b        = (const float*)d_in[8];
    float* out = (float*)d_out;

    int B = in_sizes[0] / 64;
    if (B > BMAX) B = BMAX;

    float* outO    = out;
    float* outAB   = out + (size_t)B * 64;
    float* outBias = out + (size_t)B * 64 + (size_t)B * 8192;

    const int smem_stage = 3 * STGB;                    // 107520
    const int smem_epi   = 128 * XSP * 4 + 4 * 128 * 4; // 68608
    const int smem_bytes = smem_epi > smem_stage ? smem_epi : smem_stage;
    static bool attr_set = false;
    if (!attr_set) {
        cudaFuncSetAttribute(mma_gemm1,
                             cudaFuncAttributeMaxDynamicSharedMemorySize, smem_bytes);
        cudaFuncSetAttribute(mma_gemm2,
                             cudaFuncAttributeMaxDynamicSharedMemorySize, smem_bytes);
        attr_set = true;
    }

    int nbAct = (B * INDIM + 255) / 256;
    k1_prep<<<nbAct + NB_W1 + NB_W2 + NB_B2, 256>>>(state, novelU, scale_base, scale_sp,
                                                    coef, f_w, bias_w, f_b, bias_b,
                                                    nbAct, B);

    dim3 g1(HID / 128, B / 128);
    mma_gemm1<<<g1, 256, smem_bytes>>>();

    dim3 g2(NOUT2P / 128, B / 128);
    mma_gemm2<<<g2, 256, smem_bytes>>>(outAB, outBias, outO);

    add_bias<<<(B * 64 + 255) / 256, 256>>>(outBias, outO, B * 64);
}

// round 13
// speedup vs baseline: 1.2191x; 1.0252x over previous
#include <cuda_runtime.h>
#include <cuda_fp16.h>
#include <math.h>
#include <stdint.h>

// Problem constants
#define BMAX   16384
#define INDIM  128
#define STATE  64
#define HID    1024
#define NB     8
#define KACT   (INDIM + INDIM * NB)   // 1152
#define NOUT2  (8192 + 64)            // 8256
#define NOUT2P 8320                   // padded to multiple of 128

// ---------------- scratch ----------------
__device__ float  g_x   [BMAX * INDIM];
__device__ __half g_act [BMAX * KACT];            // [b][k]
__device__ __half g_kan [BMAX * HID];             // [b][h]
__device__ __half g_W1k [KACT * HID];             // [k][o]  k-row major
__device__ __half g_W2h [(size_t)HID * NOUT2P];   // [h][n]  k-row major
__device__ float  g_b2  [NOUT2];

// ---------------- helpers ----------------
__device__ __forceinline__ void ldsm4(uint32_t addr, uint32_t& r0, uint32_t& r1,
                                      uint32_t& r2, uint32_t& r3) {
    asm volatile("ldmatrix.sync.aligned.m8n8.x4.shared.b16 {%0,%1,%2,%3}, [%4];"
                 : "=r"(r0), "=r"(r1), "=r"(r2), "=r"(r3) : "r"(addr));
}
__device__ __forceinline__ void ldsm4t(uint32_t addr, uint32_t& r0, uint32_t& r1,
                                       uint32_t& r2, uint32_t& r3) {
    asm volatile("ldmatrix.sync.aligned.m8n8.x4.trans.shared.b16 {%0,%1,%2,%3}, [%4];"
                 : "=r"(r0), "=r"(r1), "=r"(r2), "=r"(r3) : "r"(addr));
}

__device__ __forceinline__ void mma_f16(float* d, const uint32_t* a, const uint32_t* b) {
    asm volatile(
        "mma.sync.aligned.m16n8k16.row.col.f32.f16.f16.f32 "
        "{%0,%1,%2,%3}, {%4,%5,%6,%7}, {%8,%9}, {%0,%1,%2,%3};"
        : "+f"(d[0]), "+f"(d[1]), "+f"(d[2]), "+f"(d[3])
        : "r"(a[0]), "r"(a[1]), "r"(a[2]), "r"(a[3]), "r"(b[0]), "r"(b[1]));
}

__device__ __forceinline__ void cpa16(uint32_t smem, const void* g) {
    asm volatile("cp.async.cg.shared.global [%0], [%1], 16;" :: "r"(smem), "l"(g));
}
__device__ __forceinline__ void cpa_commit() { asm volatile("cp.async.commit_group;"); }
__device__ __forceinline__ void cpa_wait1()  { asm volatile("cp.async.wait_group 1;"); }

__device__ __forceinline__ uint4 pack8h(const float* v) {
    __half2 h0 = __floats2half2_rn(v[0], v[1]);
    __half2 h1 = __floats2half2_rn(v[2], v[3]);
    __half2 h2 = __floats2half2_rn(v[4], v[5]);
    __half2 h3 = __floats2half2_rn(v[6], v[7]);
    return make_uint4(*(uint32_t*)&h0, *(uint32_t*)&h1, *(uint32_t*)&h2, *(uint32_t*)&h3);
}

// ---------------- K1a: build_act + W1k + b2 ----------------
__device__ __forceinline__ float knot(int j) { return -1.0f + 0.4f * (float)(j - 3); }

#define NB_W1V ((KACT * HID / 8 + 255) / 256)     // 576
#define NB_B2V ((NOUT2 / 4 + 255) / 256)          // 9

__global__ __launch_bounds__(256) void k1a_prep(const float* __restrict__ state,
                                                const float* __restrict__ novelU,
                                                const float* __restrict__ scale_base,
                                                const float* __restrict__ scale_sp,
                                                const float* __restrict__ coef,
                                                const float* __restrict__ f_b,
                                                const float* __restrict__ bias_b,
                                                int nbAct, int B) {
    int bx = blockIdx.x, tid = threadIdx.x;
    if (bx < nbAct) {
        int idx = bx * 256 + tid;
        if (idx >= B * INDIM) return;
        int b = idx / INDIM, i = idx - b * INDIM;
        float x = (i < STATE) ? state[b * STATE + i] : novelU[b * (INDIM - STATE) + (i - STATE)];
        g_x[b * INDIM + i] = x;
        g_act[(size_t)b * KACT + i] = __float2half(__fdividef(x, 1.0f + __expf(-x)));
        float bb[11];
#pragma unroll
        for (int j = 0; j < 11; j++)
            bb[j] = (x >= knot(j) && x < knot(j + 1)) ? 1.0f : 0.0f;
#pragma unroll
        for (int ord = 1; ord <= 3; ord++) {
#pragma unroll
            for (int j = 0; j < 11 - 1; j++) {
                if (j >= 11 - ord) break;
                float l = (x - knot(j)) / (knot(j + ord) - knot(j));
                float r = (knot(j + ord + 1) - x) / (knot(j + ord + 1) - knot(j + 1));
                bb[j] = l * bb[j] + r * bb[j + 1];
            }
        }
        *(uint4*)&g_act[(size_t)b * KACT + INDIM + i * NB] = pack8h(bb);
    } else if (bx < nbAct + NB_W1V) {
        int idx8 = (bx - nbAct) * 256 + tid;
        if (idx8 >= KACT * HID / 8) return;
        int k = idx8 / (HID / 8), o8 = (idx8 % (HID / 8)) * 8;
        float v[8];
        if (k < INDIM) {
            float4 a = *(const float4*)(scale_base + k * HID + o8);
            float4 b = *(const float4*)(scale_base + k * HID + o8 + 4);
            v[0] = a.x; v[1] = a.y; v[2] = a.z; v[3] = a.w;
            v[4] = b.x; v[5] = b.y; v[6] = b.z; v[7] = b.w;
        } else {
            int kk = k - INDIM;
            int i = kk >> 3, c = kk & 7;
#pragma unroll
            for (int j = 0; j < 8; j++)
                v[j] = scale_sp[i * HID + o8 + j] * coef[((size_t)i * HID + o8 + j) * NB + c];
        }
        *(uint4*)&g_W1k[(size_t)k * HID + o8] = pack8h(v);
    } else {
        int idx4 = (bx - nbAct - NB_W1V) * 256 + tid;
        if (idx4 >= (NOUT2 + 3) / 4) return;
        int n4 = idx4 * 4;
        if (n4 + 3 < 8192) {
            *(float4*)&g_b2[n4] = *(const float4*)(f_b + n4);
        } else {
#pragma unroll
            for (int j = 0; j < 4; j++) {
                int n = n4 + j;
                if (n < NOUT2) g_b2[n] = (n < 8192) ? f_b[n] : bias_b[n - 8192];
            }
        }
    }
}

// ---------------- K1w2: W2h convert (fork stream; gemm2-only dependency) ----
#define NB_W2V (((int)((size_t)HID * NOUT2P / 8) + 255) / 256)   // 4160

__global__ __launch_bounds__(256) void k1w2_prep(const float* __restrict__ f_w,
                                                 const float* __restrict__ bias_w) {
    size_t idx8 = (size_t)blockIdx.x * 256 + threadIdx.x;
    if (idx8 >= (size_t)HID * NOUT2P / 8) return;
    int h = (int)(idx8 / (NOUT2P / 8)), n8 = (int)(idx8 % (NOUT2P / 8)) * 8;
    float v[8];
    if (n8 + 7 < 8192) {
        float4 a = *(const float4*)(f_w + (size_t)h * 8192 + n8);
        float4 b = *(const float4*)(f_w + (size_t)h * 8192 + n8 + 4);
        v[0] = a.x; v[1] = a.y; v[2] = a.z; v[3] = a.w;
        v[4] = b.x; v[5] = b.y; v[6] = b.z; v[7] = b.w;
    } else {
#pragma unroll
        for (int j = 0; j < 8; j++) {
            int n = n8 + j;
            v[j] = 0.0f;
            if (n < 8192)       v[j] = f_w[(size_t)h * 8192 + n];
            else if (n < NOUT2) v[j] = bias_w[h * 64 + (n - 8192)];
        }
    }
    *(uint4*)&g_W2h[(size_t)h * NOUT2P + n8] = pack8h(v);
}

// ---------------- FP16 tensor-core GEMM (trans-B, 2 CTAs/SM) ----------------
#define KC    64
#define SAH   72
#define SBN   136
#define A_ST  (128 * SAH * 2)
#define B_ST  (KC * SBN * 2)
#define STGB  (A_ST + B_ST)            // 35840
#define XSP   130

template<int K, int NBSTR, bool EPI2>
__device__ __forceinline__ void gemm_body(const __half* __restrict__ A,
                                          const __half* __restrict__ Bg,
                                          __half* __restrict__ C,
                                          float* __restrict__ outAB,
                                          float* __restrict__ outBias,
                                          float* __restrict__ outO,
                                          char* dynsmem, int row0, int col0) {
    uint32_t smem_addr = (uint32_t)__cvta_generic_to_shared(dynsmem);

    int tid = threadIdx.x;
    int lane = tid & 31, wid = tid >> 5;
    int m0w = (wid & 1) * 64;
    int n0w = (wid >> 1) * 32;

    int rowA  = lane & 15;
    int kAh   = 8 * (lane >> 4);
    int krowB = (lane & 7) + 8 * ((lane >> 3) & 1);
    int ncolB = 8 * (lane >> 4);

    float acc[4][4][4];
#pragma unroll
    for (int mt = 0; mt < 4; mt++)
#pragma unroll
        for (int nt = 0; nt < 4; nt++)
#pragma unroll
            for (int j = 0; j < 4; j++) acc[mt][nt][j] = 0.0f;

    const int nk = K / KC;

    auto load_stage = [&](int stg, int k0) {
        uint32_t base = smem_addr + stg * STGB;
#pragma unroll
        for (int c = 0; c < 8; c++) {
            if (c < 4) {
                int ch = tid + c * 256;
                int r = ch >> 3, off = (ch & 7) * 8;
                cpa16(base + (uint32_t)(r * SAH + off) * 2,
                      A + (size_t)(row0 + r) * K + k0 + off);
            } else {
                int ch = tid + (c - 4) * 256;
                int r = ch >> 4, off = (ch & 15) * 8;
                cpa16(base + A_ST + (uint32_t)(r * SBN + off) * 2,
                      Bg + (size_t)(k0 + r) * NBSTR + col0 + off);
            }
        }
    };

    load_stage(0, 0);
    cpa_commit();
    load_stage(1, KC);
    cpa_commit();

    for (int it = 0; it < nk; it++) {
        int cur = it % 3;
        cpa_wait1();
        __syncthreads();
        int nx = it + 2;
        if (nx < nk) load_stage(nx % 3, nx * KC);
        cpa_commit();

        uint32_t sA = smem_addr + cur * STGB;
        uint32_t sB = sA + A_ST;
#pragma unroll
        for (int ks = 0; ks < 4; ks++) {
            int kh = ks * 16;
            uint32_t a[4][4], b[2][4];
#pragma unroll
            for (int mt = 0; mt < 4; mt++) {
                uint32_t addr = sA + (uint32_t)((m0w + mt * 16 + rowA) * SAH + kh + kAh) * 2;
                ldsm4(addr, a[mt][0], a[mt][1], a[mt][2], a[mt][3]);
            }
#pragma unroll
            for (int ng = 0; ng < 2; ng++) {
                uint32_t addr = sB + (uint32_t)((kh + krowB) * SBN + n0w + ng * 16 + ncolB) * 2;
                ldsm4t(addr, b[ng][0], b[ng][1], b[ng][2], b[ng][3]);
            }
#pragma unroll
            for (int mt = 0; mt < 4; mt++)
#pragma unroll
                for (int nt = 0; nt < 4; nt++)
                    mma_f16(acc[mt][nt], a[mt], &b[nt >> 1][(nt & 1) * 2]);
        }
    }

    int gid = lane >> 2, tig = lane & 3;

#pragma unroll
    for (int mt = 0; mt < 4; mt++) {
#pragma unroll
        for (int nt = 0; nt < 4; nt++) {
            int r0r = row0 + m0w + mt * 16 + gid;
            int n   = col0 + n0w + nt * 8 + 2 * tig;
            if (!EPI2) {
                __half2 v01 = __floats2half2_rn(acc[mt][nt][0], acc[mt][nt][1]);
                __half2 v23 = __floats2half2_rn(acc[mt][nt][2], acc[mt][nt][3]);
                *(__half2*)(C + (size_t)r0r * HID + n)       = v01;
                *(__half2*)(C + (size_t)(r0r + 8) * HID + n) = v23;
            } else {
                if (n >= NOUT2) continue;
                float b0 = g_b2[n], b1 = g_b2[n + 1];
                float2 v01 = make_float2(acc[mt][nt][0] + b0, acc[mt][nt][1] + b1);
                float2 v23 = make_float2(acc[mt][nt][2] + b0, acc[mt][nt][3] + b1);
                if (n < 8192) {
                    *(float2*)(outAB + (size_t)r0r * 8192 + n)       = v01;
                    *(float2*)(outAB + (size_t)(r0r + 8) * 8192 + n) = v23;
                } else {
                    int nb = n - 8192;
                    *(float2*)(outBias + (size_t)r0r * 64 + nb)       = v01;
                    *(float2*)(outBias + (size_t)(r0r + 8) * 64 + nb) = v23;
                }
            }
        }
    }

    if (EPI2 && col0 < 8192) {
        float* xs  = (float*)dynsmem;
        float* red = xs + 128 * XSP;
        __syncthreads();
        for (int i = tid * 4; i < 128 * 128; i += 256 * 4) {
            int r = i >> 7, u = i & 127;
            float4 v = *(const float4*)(g_x + (size_t)(row0 + r) * INDIM + u);
            xs[r * XSP + u]     = v.x;
            xs[r * XSP + u + 1] = v.y;
            xs[r * XSP + u + 2] = v.z;
            xs[r * XSP + u + 3] = v.w;
        }
        __syncthreads();

        int nw = wid >> 1;
#pragma unroll
        for (int mt = 0; mt < 4; mt++) {
            int lr = m0w + mt * 16 + gid;
            float p0 = 0.0f, p1 = 0.0f;
#pragma unroll
            for (int nt = 0; nt < 4; nt++) {
                int u = n0w + nt * 8 + 2 * tig;
                float n_b0 = g_b2[col0 + u], n_b1 = g_b2[col0 + u + 1];
                float x00 = xs[lr * XSP + u],        x01 = xs[lr * XSP + u + 1];
                float x10 = xs[(lr + 8) * XSP + u],  x11 = xs[(lr + 8) * XSP + u + 1];
                p0 = fmaf(acc[mt][nt][0] + n_b0, x00, p0);
                p0 = fmaf(acc[mt][nt][1] + n_b1, x01, p0);
                p1 = fmaf(acc[mt][nt][2] + n_b0, x10, p1);
                p1 = fmaf(acc[mt][nt][3] + n_b1, x11, p1);
            }
            p0 += __shfl_xor_sync(0xffffffff, p0, 1);
            p0 += __shfl_xor_sync(0xffffffff, p0, 2);
            p1 += __shfl_xor_sync(0xffffffff, p1, 1);
            p1 += __shfl_xor_sync(0xffffffff, p1, 2);
            if (tig == 0) {
                red[nw * 128 + lr]     = p0;
                red[nw * 128 + lr + 8] = p1;
            }
        }
        __syncthreads();
        if (tid < 128) {
            float v = red[tid] + red[128 + tid] + red[256 + tid] + red[384 + tid];
            outO[(size_t)(row0 + tid) * 64 + (col0 >> 7)] = v;
        }
    }
}

__global__ __launch_bounds__(256, 2) void mma_gemm1() {
    extern __shared__ char dynsmem[];
    gemm_body<KACT, HID, false>(g_act, g_W1k, g_kan, nullptr, nullptr, nullptr,
                                dynsmem, blockIdx.y * 128, blockIdx.x * 128);
}

__global__ __launch_bounds__(256, 2) void mma_gemm2(float* __restrict__ outAB,
                                                    float* __restrict__ outBias,
                                                    float* __restrict__ outO) {
    extern __shared__ char dynsmem[];
    gemm_body<HID, NOUT2P, true>(g_kan, g_W2h, nullptr, outAB, outBias, outO,
                                 dynsmem, blockIdx.y * 128, blockIdx.x * 128);
}

// ---------------- out += bias ----------------
__global__ void add_bias(const float* __restrict__ biasOut, float* __restrict__ outO, int n) {
    int i = blockIdx.x * blockDim.x + threadIdx.x;
    if (i < n) outO[i] += biasOut[i];
}

// ---------------- launch ----------------
extern "C" void kernel_launch(void* const* d_in, const int* in_sizes, int n_in,
                              void* d_out, int out_size) {
    const float* novelU     = (const float*)d_in[0];
    const float* state      = (const float*)d_in[1];
    const float* coef       = (const float*)d_in[2];
    const float* scale_base = (const float*)d_in[3];
    const float* scale_sp   = (const float*)d_in[4];
    const float* bias_w     = (const float*)d_in[5];
    const float* bias_b     = (const float*)d_in[6];
    const float* f_w        = (const float*)d_in[7];
    const float* f_b        = (const float*)d_in[8];
    float* out = (float*)d_out;

    int B = in_sizes[0] / 64;
    if (B > BMAX) B = BMAX;

    float* outO    = out;
    float* outAB   = out + (size_t)B * 64;
    float* outBias = out + (size_t)B * 64 + (size_t)B * 8192;

    const int smem_stage = 3 * STGB;
    const int smem_epi   = 128 * XSP * 4 + 4 * 128 * 4;
    const int smem_bytes = smem_epi > smem_stage ? smem_epi : smem_stage;

    static cudaStream_t s2 = nullptr;
    static cudaEvent_t evFork = nullptr, evJoin = nullptr;
    static bool init_done = false;
    if (!init_done) {
        cudaFuncSetAttribute(mma_gemm1,
                             cudaFuncAttributeMaxDynamicSharedMemorySize, smem_bytes);
        cudaFuncSetAttribute(mma_gemm2,
                             cudaFuncAttributeMaxDynamicSharedMemorySize, smem_bytes);
        cudaStreamCreateWithFlags(&s2, cudaStreamNonBlocking);
        cudaEventCreateWithFlags(&evFork, cudaEventDisableTiming);
        cudaEventCreateWithFlags(&evJoin, cudaEventDisableTiming);
        init_done = true;
    }

    // fork: W2h convert runs concurrently with k1a + gemm1 (only gemm2 needs it)
    cudaEventRecord(evFork, 0);
    cudaStreamWaitEvent(s2, evFork, 0);
    k1w2_prep<<<NB_W2V, 256, 0, s2>>>(f_w, bias_w);
    cudaEventRecord(evJoin, s2);

    int nbAct = (B * INDIM + 255) / 256;
    k1a_prep<<<nbAct + NB_W1V + NB_B2V, 256>>>(state, novelU, scale_base, scale_sp,
                                               coef, f_b, bias_b, nbAct, B);

    dim3 g1(HID / 128, B / 128);
    mma_gemm1<<<g1, 256, smem_bytes>>>();

    cudaStreamWaitEvent(0, evJoin, 0);   // join before gemm2
    dim3 g2(NOUT2P / 128, B / 128);
    mma_gemm2<<<g2, 256, smem_bytes>>>(outAB, outBias, outO);

    add_bias<<<(B * 64 + 255) / 256, 256>>>(outBias, outO, B * 64);
}